// round 16
// baseline (speedup 1.0000x reference)
#include <cuda_runtime.h>
#include <cuda_bf16.h>

// SoftmaxMarginLoss (ArcFace margin + scaled softmax CE, mean over batch).
// B=512, C=100000, fp32 logits in [-1,1), labels int32-or-int64 (sniffed).
//
// R15 winner (36.96us: single wave, GRID=1024, PF_DIST=8 prefetch, FFMA2
// exp2-bit-splice) with ONE change: 256-bit loads (ld.global.nc.v8.b32)
// instead of 128-bit __ldcs -> half the LDG count, 1KB/warp per scoreboard
// wait, cleaner L1tex request stream.

#define NUM_CLASSES 100000
#define BATCH       512
#define CHUNKS      2
#define CHUNK_ELEMS (NUM_CLASSES / CHUNKS)   // 50000
#define NVEC8       (CHUNK_ELEMS / 8)        // 6250 8-float vectors per CTA
#define TPB         256
#define GRID        (BATCH * CHUNKS)         // 1024 -> single co-resident wave
#define PF_DIST     8                        // prefetch lead, iterations

__device__ float        g_partials[GRID];
__device__ float        g_tn[BATCH];
__device__ unsigned int g_count;             // zero-init; self-resets each run

// ---- constants for 2^96 * exp(64x - 64) = 2^(x*K + C) ----
#define KF 92.33248261689366f                 /* 64*log2(e) */
#define CF 3.667517383106341f                 /* 96 - 64*log2(e) */
#define MAGICF 12582912.0f                    /* 1.5 * 2^23 */
#define LN2_96 66.54212933375475f             /* 96*ln(2) */

__device__ __forceinline__ unsigned long long pk2(float x) {
    unsigned int b = __float_as_uint(x);
    return ((unsigned long long)b << 32) | (unsigned long long)b;
}

struct ExpConsts {
    unsigned long long K2, C2, M2, nM2, NEG1, P3, P2, P1, P0;
};

// acc2 += 2^(x*K + C) for both packed halves. Heavy math on FFMA2.
__device__ __forceinline__ void exp2pair_acc(unsigned long long x2,
                                             unsigned long long& acc2,
                                             const ExpConsts& c)
{
    unsigned long long u2, t2, n2, f2, p2, e2;
    asm("fma.rn.f32x2 %0, %1, %2, %3;" : "=l"(u2) : "l"(x2), "l"(c.K2), "l"(c.C2));
    asm("add.rn.f32x2 %0, %1, %2;"     : "=l"(t2) : "l"(u2), "l"(c.M2));   // rne(u)+MAGIC
    asm("add.rn.f32x2 %0, %1, %2;"     : "=l"(n2) : "l"(t2), "l"(c.nM2));  // n = rne(u)
    asm("fma.rn.f32x2 %0, %1, %2, %3;" : "=l"(f2) : "l"(n2), "l"(c.NEG1), "l"(u2)); // f=u-n
    asm("fma.rn.f32x2 %0, %1, %2, %3;" : "=l"(p2) : "l"(c.P3), "l"(f2), "l"(c.P2));
    asm("fma.rn.f32x2 %0, %1, %2, %3;" : "=l"(p2) : "l"(p2), "l"(f2), "l"(c.P1));
    asm("fma.rn.f32x2 %0, %1, %2, %3;" : "=l"(p2) : "l"(p2), "l"(f2), "l"(c.P0));
    // exponent splice per half: e_bits = p_bits + (t_bits << 23)  (== p * 2^n)
    unsigned int tlo, thi, plo, phi;
    asm("mov.b64 {%0,%1}, %2;" : "=r"(tlo), "=r"(thi) : "l"(t2));
    asm("mov.b64 {%0,%1}, %2;" : "=r"(plo), "=r"(phi) : "l"(p2));
    unsigned int elo = plo + (tlo << 23);
    unsigned int ehi = phi + (thi << 23);
    asm("mov.b64 %0, {%1,%2};" : "=l"(e2) : "r"(elo), "r"(ehi));
    asm("add.rn.f32x2 %0, %1, %2;" : "=l"(acc2) : "l"(acc2), "l"(e2));
}

__device__ __forceinline__ float warp_sum(float v) {
    #pragma unroll
    for (int o = 16; o > 0; o >>= 1) v += __shfl_down_sync(0xFFFFFFFFu, v, o);
    return v;
}

// precise scalar 2^96*exp(64y-64) (MUFU exp2f fine off the hot path)
__device__ __forceinline__ float exp_s64_scaled(float y) {
    return exp2f(fmaf(y, KF, CF));
}

__device__ __forceinline__ int clampL(long long L) {
    if (L < 0) L = 0;
    if (L >= NUM_CLASSES) L = NUM_CLASSES - 1;
    return (int)L;
}

__global__ __launch_bounds__(TPB)
void fused_kernel(const float* __restrict__ logits,
                  const void*  __restrict__ labels_raw,
                  float*       __restrict__ out)
{
    const int b   = blockIdx.x;
    const int row = b >> 1;
    const int chk = b & 1;
    const char* base =
        (const char*)(logits + (size_t)row * NUM_CLASSES + (size_t)chk * CHUNK_ELEMS);

    __shared__ float red[TPB / 32];
    __shared__ unsigned int ticket;
    __shared__ int odd_or;

    // ---- chk==0 CTAs: start sniff + both candidate gathers BEFORE the loop ----
    const int* w = (const int*)labels_raw;
    float t32 = 0.f, t64 = 0.f;
    if (chk == 0) {
        if (threadIdx.x == 0) odd_or = 0;
        __syncthreads();
        if (w[2 * threadIdx.x + 1] != 0) atomicOr(&odd_or, 1);
        if (threadIdx.x == 0) {
            const int L32 = clampL((long long)w[row]);
            const int L64 = clampL(((const long long*)labels_raw)[row]);
            t32 = logits[(size_t)row * NUM_CLASSES + L32];
            t64 = logits[(size_t)row * NUM_CLASSES + L64];
        }
    }

    ExpConsts c;
    c.K2 = pk2(KF);  c.C2 = pk2(CF);  c.M2 = pk2(MAGICF);  c.nM2 = pk2(-MAGICF);
    c.NEG1 = pk2(-1.0f);
    c.P3 = pk2(0.05550410866482158f);
    c.P2 = pk2(0.2402265069591007f);
    c.P1 = pk2(0.6931471805599453f);
    c.P0 = pk2(1.0f);

    unsigned long long ac0 = 0ull, ac1 = 0ull, ac2 = 0ull, ac3 = 0ull;
    const bool pf_lane = ((threadIdx.x & 3) == 0);   // one lane per 128B line

    #pragma unroll 2
    for (int i = threadIdx.x; i < NVEC8; i += TPB) {
        int pfi = i + PF_DIST * TPB;
        if (pfi > NVEC8 - 1) pfi = NVEC8 - 1;        // clamp inside the chunk
        if (pf_lane)
            asm volatile("prefetch.global.L2 [%0];" :: "l"(base + (size_t)pfi * 32));
        // 256-bit load: 8 consecutive floats, 32B-aligned
        unsigned int r0, r1, r2, r3, r4, r5, r6, r7;
        asm("ld.global.nc.v8.b32 {%0,%1,%2,%3,%4,%5,%6,%7}, [%8];"
            : "=r"(r0), "=r"(r1), "=r"(r2), "=r"(r3),
              "=r"(r4), "=r"(r5), "=r"(r6), "=r"(r7)
            : "l"(base + (size_t)i * 32));
        unsigned long long xa, xb, xc, xd;
        asm("mov.b64 %0, {%1,%2};" : "=l"(xa) : "r"(r0), "r"(r1));
        asm("mov.b64 %0, {%1,%2};" : "=l"(xb) : "r"(r2), "r"(r3));
        asm("mov.b64 %0, {%1,%2};" : "=l"(xc) : "r"(r4), "r"(r5));
        asm("mov.b64 %0, {%1,%2};" : "=l"(xd) : "r"(r6), "r"(r7));
        exp2pair_acc(xa, ac0, c);
        exp2pair_acc(xb, ac1, c);
        exp2pair_acc(xc, ac2, c);
        exp2pair_acc(xd, ac3, c);
    }

    unsigned long long sA, sB;
    asm("add.rn.f32x2 %0, %1, %2;" : "=l"(sA) : "l"(ac0), "l"(ac1));
    asm("add.rn.f32x2 %0, %1, %2;" : "=l"(sB) : "l"(ac2), "l"(ac3));
    asm("add.rn.f32x2 %0, %1, %2;" : "=l"(sA) : "l"(sA), "l"(sB));
    float a0, a1;
    asm("mov.b64 {%0,%1}, %2;" : "=f"(a0), "=f"(a1) : "l"(sA));
    float s = a0 + a1;

    s = warp_sum(s);
    const int lane = threadIdx.x & 31, wid = threadIdx.x >> 5;
    if (lane == 0) red[wid] = s;
    __syncthreads();
    if (threadIdx.x == 0) {
        float t = 0.f;
        #pragma unroll
        for (int k = 0; k < TPB / 32; k++) t += red[k];

        if (chk == 0) {
            // margin fixup for this row, folded into the partial
            const float tt = (odd_or == 0) ? t64 : t32;   // is_i64 -> t64
            const float COSM = 0.87758256189037276f;      // cos(0.5)
            const float SINM = 0.47942553860420301f;      // sin(0.5)
            const float EPS  = 1e-7f;
            float tc = fminf(fmaxf(tt, -1.0f + EPS), 1.0f - EPS);
            float tn = tc * COSM - sqrtf(fmaxf(1.0f - tc * tc, 0.0f)) * SINM;
            t += exp_s64_scaled(tn) - exp_s64_scaled(tt);
            g_tn[row] = tn;
        }
        g_partials[b] = t;
        __threadfence();
        ticket = atomicAdd(&g_count, 1u);
    }
    __syncthreads();
    if (ticket != GRID - 1) return;

    // ====== last block: pure reduction (no gathers, no sniff) ======
    const int i = threadIdx.x;
    float vsum = 0.f;
    #pragma unroll
    for (int rr = 0; rr < BATCH / TPB; rr++) {
        const int r = i + rr * TPB;
        float S = g_partials[2 * r] + g_partials[2 * r + 1];
        // nll = 64 + log(S) - 96*ln2 - 64*tn
        vsum += 64.0f + logf(S) - LN2_96 - 64.0f * g_tn[r];
    }

    float v = warp_sum(vsum);
    if (lane == 0) red[wid] = v;
    __syncthreads();
    if (wid == 0) {
        v = (lane < TPB / 32) ? red[lane] : 0.f;
        v = warp_sum(v);
        if (lane == 0) {
            out[0] = v * (1.0f / (float)BATCH);
            g_count = 0;   // reset for next graph replay
        }
    }
}

extern "C" void kernel_launch(void* const* d_in, const int* in_sizes, int n_in,
                              void* d_out, int out_size) {
    const float* logits = (const float*)d_in[0];
    const void*  labels = (const void*)d_in[1];
    if (n_in >= 2 && in_sizes[1] > in_sizes[0]) {   // defensive swap
        labels = (const void*)d_in[0];
        logits = (const float*)d_in[1];
    }
    fused_kernel<<<GRID, TPB>>>(logits, labels, (float*)d_out);
}

// round 17
// speedup vs baseline: 1.3089x; 1.3089x over previous
#include <cuda_runtime.h>
#include <cuda_bf16.h>

// SoftmaxMarginLoss (ArcFace margin + scaled softmax CE, mean over batch).
// B=512, C=100000, fp32 logits in [-1,1), labels int32-or-int64 (sniffed).
//
// FINAL (== R15 champion, 36.96us): single fused kernel, single wave.
//   GRID=1024 CTAs (one co-resident wave) x 256 thr; each CTA sums
//   2^96*exp(64x-64) over a 50000-elem half-row: unroll-2 strided __ldcs
//   (LDG.E.128) loop with deep L2 prefetch (PF_DIST=8, clamped index, one
//   prefetch lane per 128B line), packed f32x2 FMA (FFMA2) exp2-bit-splice
//   (single pass, no max pass, no MUFU in the hot loop).
//   Each row's chk==0 CTA sniffs the label dtype and issues both candidate
//   target-logit gathers BEFORE the main loop (they complete under it), then
//   folds the ArcFace margin-fixup delta into its partial and stores tn.
//   Global last CTA (atomic ticket) sums partials, logf, NLL, mean -> out[0].

#define NUM_CLASSES 100000
#define BATCH       512
#define CHUNKS      2
#define CHUNK_ELEMS (NUM_CLASSES / CHUNKS)   // 50000
#define NVEC        (CHUNK_ELEMS / 4)        // 12500 float4 per CTA
#define TPB         256
#define GRID        (BATCH * CHUNKS)         // 1024 -> single co-resident wave
#define PF_DIST     8                        // prefetch lead, iterations

__device__ float        g_partials[GRID];
__device__ float        g_tn[BATCH];
__device__ unsigned int g_count;             // zero-init; self-resets each run

// ---- constants for 2^96 * exp(64x - 64) = 2^(x*K + C) ----
#define KF 92.33248261689366f                 /* 64*log2(e) */
#define CF 3.667517383106341f                 /* 96 - 64*log2(e) */
#define MAGICF 12582912.0f                    /* 1.5 * 2^23 */
#define LN2_96 66.54212933375475f             /* 96*ln(2) */

__device__ __forceinline__ unsigned long long pk2(float x) {
    unsigned int b = __float_as_uint(x);
    return ((unsigned long long)b << 32) | (unsigned long long)b;
}

struct ExpConsts {
    unsigned long long K2, C2, M2, nM2, NEG1, P3, P2, P1, P0;
};

// acc2 += 2^(x*K + C) for both packed halves. Heavy math on FFMA2.
__device__ __forceinline__ void exp2pair_acc(unsigned long long x2,
                                             unsigned long long& acc2,
                                             const ExpConsts& c)
{
    unsigned long long u2, t2, n2, f2, p2, e2;
    asm("fma.rn.f32x2 %0, %1, %2, %3;" : "=l"(u2) : "l"(x2), "l"(c.K2), "l"(c.C2));
    asm("add.rn.f32x2 %0, %1, %2;"     : "=l"(t2) : "l"(u2), "l"(c.M2));   // rne(u)+MAGIC
    asm("add.rn.f32x2 %0, %1, %2;"     : "=l"(n2) : "l"(t2), "l"(c.nM2));  // n = rne(u)
    asm("fma.rn.f32x2 %0, %1, %2, %3;" : "=l"(f2) : "l"(n2), "l"(c.NEG1), "l"(u2)); // f=u-n
    asm("fma.rn.f32x2 %0, %1, %2, %3;" : "=l"(p2) : "l"(c.P3), "l"(f2), "l"(c.P2));
    asm("fma.rn.f32x2 %0, %1, %2, %3;" : "=l"(p2) : "l"(p2), "l"(f2), "l"(c.P1));
    asm("fma.rn.f32x2 %0, %1, %2, %3;" : "=l"(p2) : "l"(p2), "l"(f2), "l"(c.P0));
    // exponent splice per half: e_bits = p_bits + (t_bits << 23)  (== p * 2^n)
    unsigned int tlo, thi, plo, phi;
    asm("mov.b64 {%0,%1}, %2;" : "=r"(tlo), "=r"(thi) : "l"(t2));
    asm("mov.b64 {%0,%1}, %2;" : "=r"(plo), "=r"(phi) : "l"(p2));
    unsigned int elo = plo + (tlo << 23);
    unsigned int ehi = phi + (thi << 23);
    asm("mov.b64 %0, {%1,%2};" : "=l"(e2) : "r"(elo), "r"(ehi));
    asm("add.rn.f32x2 %0, %1, %2;" : "=l"(acc2) : "l"(acc2), "l"(e2));
}

__device__ __forceinline__ float warp_sum(float v) {
    #pragma unroll
    for (int o = 16; o > 0; o >>= 1) v += __shfl_down_sync(0xFFFFFFFFu, v, o);
    return v;
}

// precise scalar 2^96*exp(64y-64) (MUFU exp2f fine off the hot path)
__device__ __forceinline__ float exp_s64_scaled(float y) {
    return exp2f(fmaf(y, KF, CF));
}

__device__ __forceinline__ int clampL(long long L) {
    if (L < 0) L = 0;
    if (L >= NUM_CLASSES) L = NUM_CLASSES - 1;
    return (int)L;
}

__global__ __launch_bounds__(TPB)
void fused_kernel(const float* __restrict__ logits,
                  const void*  __restrict__ labels_raw,
                  float*       __restrict__ out)
{
    const int b   = blockIdx.x;
    const int row = b >> 1;
    const int chk = b & 1;
    const float4* base =
        (const float4*)(logits + (size_t)row * NUM_CLASSES + (size_t)chk * CHUNK_ELEMS);

    __shared__ float red[TPB / 32];
    __shared__ unsigned int ticket;
    __shared__ int odd_or;

    // ---- chk==0 CTAs: start sniff + both candidate gathers BEFORE the loop ----
    const int* w = (const int*)labels_raw;
    float t32 = 0.f, t64 = 0.f;
    if (chk == 0) {
        if (threadIdx.x == 0) odd_or = 0;
        __syncthreads();
        if (w[2 * threadIdx.x + 1] != 0) atomicOr(&odd_or, 1);
        if (threadIdx.x == 0) {
            const int L32 = clampL((long long)w[row]);
            const int L64 = clampL(((const long long*)labels_raw)[row]);
            t32 = logits[(size_t)row * NUM_CLASSES + L32];
            t64 = logits[(size_t)row * NUM_CLASSES + L64];
        }
    }

    ExpConsts c;
    c.K2 = pk2(KF);  c.C2 = pk2(CF);  c.M2 = pk2(MAGICF);  c.nM2 = pk2(-MAGICF);
    c.NEG1 = pk2(-1.0f);
    c.P3 = pk2(0.05550410866482158f);
    c.P2 = pk2(0.2402265069591007f);
    c.P1 = pk2(0.6931471805599453f);
    c.P0 = pk2(1.0f);

    unsigned long long ac0 = 0ull, ac1 = 0ull;
    const bool pf_lane = ((threadIdx.x & 7) == 0);   // one lane per 128B line

    #pragma unroll 2
    for (int i = threadIdx.x; i < NVEC; i += TPB) {
        int pfi = i + PF_DIST * TPB;
        if (pfi > NVEC - 1) pfi = NVEC - 1;          // clamp inside the chunk
        if (pf_lane)
            asm volatile("prefetch.global.L2 [%0];" :: "l"(base + pfi));
        float4 v = __ldcs(base + i);
        unsigned long long xa, xb;
        asm("mov.b64 %0, {%1,%2};" : "=l"(xa) : "f"(v.x), "f"(v.y));
        asm("mov.b64 %0, {%1,%2};" : "=l"(xb) : "f"(v.z), "f"(v.w));
        exp2pair_acc(xa, ac0, c);
        exp2pair_acc(xb, ac1, c);
    }

    unsigned long long sA;
    asm("add.rn.f32x2 %0, %1, %2;" : "=l"(sA) : "l"(ac0), "l"(ac1));
    float a0, a1;
    asm("mov.b64 {%0,%1}, %2;" : "=f"(a0), "=f"(a1) : "l"(sA));
    float s = a0 + a1;

    s = warp_sum(s);
    const int lane = threadIdx.x & 31, wid = threadIdx.x >> 5;
    if (lane == 0) red[wid] = s;
    __syncthreads();
    if (threadIdx.x == 0) {
        float t = 0.f;
        #pragma unroll
        for (int k = 0; k < TPB / 32; k++) t += red[k];

        if (chk == 0) {
            // margin fixup for this row, folded into the partial
            const float tt = (odd_or == 0) ? t64 : t32;   // is_i64 -> t64
            const float COSM = 0.87758256189037276f;      // cos(0.5)
            const float SINM = 0.47942553860420301f;      // sin(0.5)
            const float EPS  = 1e-7f;
            float tc = fminf(fmaxf(tt, -1.0f + EPS), 1.0f - EPS);
            float tn = tc * COSM - sqrtf(fmaxf(1.0f - tc * tc, 0.0f)) * SINM;
            t += exp_s64_scaled(tn) - exp_s64_scaled(tt);
            g_tn[row] = tn;
        }
        g_partials[b] = t;
        __threadfence();
        ticket = atomicAdd(&g_count, 1u);
    }
    __syncthreads();
    if (ticket != GRID - 1) return;

    // ====== last block: pure reduction (no gathers, no sniff) ======
    const int i = threadIdx.x;
    float vsum = 0.f;
    #pragma unroll
    for (int rr = 0; rr < BATCH / TPB; rr++) {
        const int r = i + rr * TPB;
        float S = g_partials[2 * r] + g_partials[2 * r + 1];
        // nll = 64 + log(S) - 96*ln2 - 64*tn
        vsum += 64.0f + logf(S) - LN2_96 - 64.0f * g_tn[r];
    }

    float v = warp_sum(vsum);
    if (lane == 0) red[wid] = v;
    __syncthreads();
    if (wid == 0) {
        v = (lane < TPB / 32) ? red[lane] : 0.f;
        v = warp_sum(v);
        if (lane == 0) {
            out[0] = v * (1.0f / (float)BATCH);
            g_count = 0;   // reset for next graph replay
        }
    }
}

extern "C" void kernel_launch(void* const* d_in, const int* in_sizes, int n_in,
                              void* d_out, int out_size) {
    const float* logits = (const float*)d_in[0];
    const void*  labels = (const void*)d_in[1];
    if (n_in >= 2 && in_sizes[1] > in_sizes[0]) {   // defensive swap
        labels = (const void*)d_in[0];
        logits = (const float*)d_in[1];
    }
    fused_kernel<<<GRID, TPB>>>(logits, labels, (float*)d_out);
}